// round 6
// baseline (speedup 1.0000x reference)
#include <cuda_runtime.h>
#include <cstdint>

#define NNF 128
#define MID 32
typedef unsigned long long u64;

// Staging + final tables
__device__ float g_stage[3][32][6][32];
__device__ float g_R[9][NNF];
__device__ float g_S[6][NNF];
__device__ unsigned int g_ctr = 0;   // wraps back to 0 every launch (atomicInc)

// ---- packed f32x2 helpers -------------------------------------------------
__device__ __forceinline__ u64 pk2(float lo, float hi) {
    u64 r; asm("mov.b64 %0,{%1,%2};" : "=l"(r) : "f"(lo), "f"(hi)); return r;
}
__device__ __forceinline__ void upk2(u64 a, float& lo, float& hi) {
    asm("mov.b64 {%0,%1},%2;" : "=f"(lo), "=f"(hi) : "l"(a));
}
__device__ __forceinline__ u64 fma2(u64 a, u64 b, u64 c) {
    u64 d; asm("fma.rn.f32x2 %0,%1,%2,%3;" : "=l"(d) : "l"(a), "l"(b), "l"(c)); return d;
}
__device__ __forceinline__ u64 mul2(u64 a, u64 b) {
    u64 d; asm("mul.rn.f32x2 %0,%1,%2;" : "=l"(d) : "l"(a), "l"(b)); return d;
}
__device__ __forceinline__ u64 add2(u64 a, u64 b) {
    u64 d; asm("add.rn.f32x2 %0,%1,%2;" : "=l"(d) : "l"(a), "l"(b)); return d;
}

// ---- mbarrier / bulk-async helpers ----------------------------------------
__device__ __forceinline__ uint32_t smem_u32(const void* p) {
    uint32_t a;
    asm("{ .reg .u64 t; cvta.to.shared.u64 t, %1; cvt.u32.u64 %0, t; }"
        : "=r"(a) : "l"(p));
    return a;
}
__device__ __forceinline__ void mbar_init(uint32_t a, uint32_t cnt) {
    asm volatile("mbarrier.init.shared.b64 [%0], %1;" :: "r"(a), "r"(cnt) : "memory");
}
__device__ __forceinline__ void mbar_expect_tx(uint32_t a, uint32_t bytes) {
    asm volatile("mbarrier.arrive.expect_tx.shared.b64 _, [%0], %1;"
                 :: "r"(a), "r"(bytes) : "memory");
}
__device__ __forceinline__ void mbar_wait(uint32_t a, uint32_t parity) {
    asm volatile(
        "{\n\t.reg .pred P;\n"
        "W_%=:\n\t"
        "mbarrier.try_wait.parity.acquire.cta.shared::cta.b64 P, [%0], %1, 0x989680;\n\t"
        "@P bra D_%=;\n\t"
        "bra W_%=;\n"
        "D_%=:\n\t}"
        :: "r"(a), "r"(parity) : "memory");
}
__device__ __forceinline__ void bulk_g2s(uint32_t dst, const void* src,
                                         uint32_t bytes, uint32_t mbar) {
    asm volatile(
        "cp.async.bulk.shared::cluster.global.mbarrier::complete_tx::bytes "
        "[%0], [%1], %2, [%3];"
        :: "r"(dst), "l"(src), "r"(bytes), "r"(mbar) : "memory");
}

// ---------------------------------------------------------------------------
// Fused precompute: 96 blocks do stage 1 (3 families x 32 u-slices), the
// last-finishing block does stage 2 (u-reduction + Wd projection + scales).
// __launch_bounds__(1024,1) caps regs at 64 so the 1024-thread launch fits
// the register file (stage-2 spill is irrelevant: tiny, latency-bound).
// ---------------------------------------------------------------------------
__global__ void __launch_bounds__(1024, 1) precompute_kernel(
    const float* __restrict__ Wa_s, const float* __restrict__ Wa_v,
    const float* __restrict__ b_a,  const float* __restrict__ Wb_s,
    const float* __restrict__ Wb_v, const float* __restrict__ b_b,
    const float* __restrict__ W_ss, const float* __restrict__ W_vv,
    const float* __restrict__ W_sv, const float* __restrict__ W_vs,
    const float* __restrict__ Wd_s, const float* __restrict__ Wd_v)
{
    __shared__ float sA[MID], sB[MID], sC[MID], sAv[MID], sBv[MID];
    __shared__ float buf[6][32][33];
    __shared__ unsigned int is_last;

    const int tid = threadIdx.x;
    const int fam = blockIdx.x >> 5;
    const int u   = blockIdx.x & 31;
    if (tid < MID) {
        sA[tid]  = Wa_s[tid];
        sB[tid]  = Wb_s[tid];
        sC[tid]  = b_a[tid] + b_b[tid];
        sAv[tid] = Wa_v[tid];
        sBv[tid] = Wb_v[tid];
    }
    __syncthreads();

    const int v = tid >> 5;
    const int w = tid & 31;
    const int idx = u * 1024 + v * 32 + w;
    int nk;

    if (fam == 0) {
        float t = W_ss[idx];
        float Au = sA[u], Bu = sB[u], Cu = sC[u];
        float Av = sA[v], Bv = sB[v], Cv = sC[v];
        buf[0][v][w] = (Au * Av) * t;
        buf[1][v][w] = (Au * Bv + Bu * Av) * t;
        buf[2][v][w] = (Bu * Bv) * t;
        buf[3][v][w] = (Au * Cv + Cu * Av) * t;
        buf[4][v][w] = (Bu * Cv + Cu * Bv) * t;
        buf[5][v][w] = (Cu * Cv) * t;
        nk = 6;
    } else if (fam == 1) {
        float t = W_vv[idx];
        float Avu = sAv[u], Bvu = sBv[u], Avv = sAv[v], Bvv = sBv[v];
        buf[0][v][w] = (Avu * Avv) * t;
        buf[1][v][w] = (Avu * Bvv + Bvu * Avv) * t;
        buf[2][v][w] = (Bvu * Bvv) * t;
        nk = 3;
    } else {
        float tsv = W_sv[idx];
        float tvs = W_vs[idx];
        float Au = sA[u], Bu = sB[u], Cu = sC[u];
        float Avu = sAv[u], Bvu = sBv[u];
        float Av = sA[v], Bv = sB[v], Cv = sC[v];
        float Avv = sAv[v], Bvv = sBv[v];
        buf[0][v][w] = Au * Avv * tsv + Avu * Av * tvs;
        buf[1][v][w] = Bu * Avv * tsv + Avu * Bv * tvs;
        buf[2][v][w] = Cu * Avv * tsv + Avu * Cv * tvs;
        buf[3][v][w] = Au * Bvv * tsv + Bvu * Av * tvs;
        buf[4][v][w] = Bu * Bvv * tsv + Bvu * Bv * tvs;
        buf[5][v][w] = Cu * Bvv * tsv + Bvu * Cv * tvs;
        nk = 6;
    }
    __syncthreads();

    if (tid < nk * 32) {
        const int k = tid >> 5, ww = tid & 31;
        float s = 0.f;
        #pragma unroll
        for (int vv = 0; vv < 32; vv++) s += buf[k][vv][ww];
        g_stage[fam][u][k][ww] = s;
    }

    // ---- last block performs stage 2 ----
    __threadfence();
    __syncthreads();
    if (tid == 0) {
        unsigned int old = atomicInc(&g_ctr, 95u);  // wraps to 0 after 96 incs
        is_last = (old == 95u);
    }
    __syncthreads();
    if (!is_last) return;
    __threadfence();

    __shared__ float sM[9][32], sG[3][32], sH[3][32];
    if (tid < 480) {
        const int ww = tid & 31;
        float s = 0.f;
        if (tid < 192) {
            const int k = tid >> 5;
            #pragma unroll
            for (int uu = 0; uu < 32; uu++) s += g_stage[0][uu][k][ww];
            sM[k][ww] = s;
        } else if (tid < 288) {
            const int k = (tid - 192) >> 5;
            #pragma unroll
            for (int uu = 0; uu < 32; uu++) s += g_stage[1][uu][k][ww];
            sM[6 + k][ww] = s;
        } else {
            const int k = (tid - 288) >> 5;
            #pragma unroll
            for (int uu = 0; uu < 32; uu++) s += g_stage[2][uu][k][ww];
            if (k < 3) sG[k][ww] = s; else sH[k - 3][ww] = s;
        }
    }
    __syncthreads();

    if (tid < NNF) {
        const int vp = tid;
        const double INV_SQRT3 = 0.5773502691896258;
        const double PW_QQ_S = 0.02209708691207961;
        const double PW_QQ_V = 0.03827327723098713;
        const double PW_DOWN = 0.011048543456039805;
        const float scR  = (float)(PW_DOWN * PW_QQ_S);
        const float scR3 = (float)(PW_DOWN * PW_QQ_S * INV_SQRT3);
        const float scS  = (float)(PW_DOWN * INV_SQRT3 * PW_QQ_V * INV_SQRT3);

        #pragma unroll
        for (int k = 0; k < 9; k++) {
            float s = 0.f;
            #pragma unroll
            for (int uu = 0; uu < MID; uu++) s += sM[k][uu] * Wd_s[uu * NNF + vp];
            g_R[k][vp] = s * (k < 6 ? scR : scR3);
        }
        #pragma unroll
        for (int k = 0; k < 3; k++) {
            float sg = 0.f, sh = 0.f;
            #pragma unroll
            for (int uu = 0; uu < MID; uu++) {
                float wd = Wd_v[uu * NNF + vp];
                sg += sG[k][uu] * wd;
                sh += sH[k][uu] * wd;
            }
            g_S[k][vp]     = sg * scS;
            g_S[3 + k][vp] = sh * scS;
        }
    }
}

// ---------------------------------------------------------------------------
// Per-node partial (per-lane, 4 features) using packed f32x2 math.
// ---------------------------------------------------------------------------
__device__ __forceinline__ float node_partial(
    const u64 R2[9][2], const u64 S2[6][2],
    float4 fs, float4 fv0, float4 fv1, float4 fv2, float4 q0, float4 qi)
{
    const float a = qi.x, b = q0.x;
    const float g0 = qi.y, g1 = qi.z, g2 = qi.w;
    const float d0 = q0.y, d1 = q0.z, d2 = q0.w;
    const float ca2 = a * a, cab = a * b, cb2 = b * b;
    const float cg2 = g0 * g0 + g1 * g1 + g2 * g2;
    const float cgd = g0 * d0 + g1 * d1 + g2 * d2;
    const float cd2 = d0 * d0 + d1 * d1 + d2 * d2;

    const u64 C0 = pk2(ca2, ca2), C1 = pk2(cab, cab), C2 = pk2(cb2, cb2);
    const u64 CA = pk2(a, a),     CB = pk2(b, b);
    const u64 C6 = pk2(cg2, cg2), C7 = pk2(cgd, cgd), C8 = pk2(cd2, cd2);
    const u64 G0 = pk2(g0, g0), G1 = pk2(g1, g1), G2 = pk2(g2, g2);
    const u64 D0 = pk2(d0, d0), D1 = pk2(d1, d1), D2 = pk2(d2, d2);

    const float fv[12] = {fv0.x, fv0.y, fv0.z, fv0.w,
                          fv1.x, fv1.y, fv1.z, fv1.w,
                          fv2.x, fv2.y, fv2.z, fv2.w};
    const u64 fs2[2] = { pk2(fs.x, fs.y), pk2(fs.z, fs.w) };

    u64 acc = pk2(0.f, 0.f);
    #pragma unroll
    for (int h = 0; h < 2; h++) {
        u64 t = fma2(C0, R2[0][h], R2[5][h]);
        t = fma2(C1, R2[1][h], t);
        t = fma2(C2, R2[2][h], t);
        t = fma2(CA, R2[3][h], t);
        t = fma2(CB, R2[4][h], t);
        t = fma2(C6, R2[6][h], t);
        t = fma2(C7, R2[7][h], t);
        t = fma2(C8, R2[8][h], t);
        acc = fma2(fs2[h], t, acc);

        const u64 x0 = pk2(fv[6 * h + 0], fv[6 * h + 3]);
        const u64 x1 = pk2(fv[6 * h + 1], fv[6 * h + 4]);
        const u64 x2 = pk2(fv[6 * h + 2], fv[6 * h + 5]);
        u64 xg = mul2(G0, x0);
        xg = fma2(G1, x1, xg);
        xg = fma2(G2, x2, xg);
        u64 xd = mul2(D0, x0);
        xd = fma2(D1, x1, xd);
        xd = fma2(D2, x2, xd);
        u64 sg = fma2(CA, S2[0][h], S2[2][h]);
        sg = fma2(CB, S2[1][h], sg);
        u64 sh = fma2(CA, S2[3][h], S2[5][h]);
        sh = fma2(CB, S2[4][h], sh);
        acc = fma2(xg, sg, acc);
        acc = fma2(xd, sh, acc);
    }
    float lo, hi;
    upk2(acc, lo, hi);
    return lo + hi;
}

// ---------------------------------------------------------------------------
// Energy kernel: persistent blocks; TWO independent 8-warp pipelines per
// block (group 0 = warps 0-7, group 1 = warps 8-15), each with its own
// 3-stage cp.async.bulk ring over 16-node tiles. Group bubbles interleave.
// ---------------------------------------------------------------------------
#define TILE_NODES   16
#define STAGES       3
#define NF_BYTES     (TILE_NODES * 4 * NNF * 4)       // 32768
#define CH_BYTES     (TILE_NODES * 4 * 4)             // 256
#define STAGE_BYTES  (NF_BYTES + 2 * CH_BYTES)        // 33280
#define SMEM_STAGE0  128
#define SMEM_TOTAL   (SMEM_STAGE0 + 2 * STAGES * STAGE_BYTES)   // 199808

__global__ void __launch_bounds__(512, 1) energy_kernel(
    const float* __restrict__ nf,
    const float* __restrict__ c0,
    const float* __restrict__ ci,
    float* __restrict__ out, int N)
{
    extern __shared__ char smem[];
    const uint32_t smem_base = smem_u32(smem);
    const int tid   = threadIdx.x;
    const int lane  = tid & 31;
    const int wid   = tid >> 5;          // 0..15
    const int grp   = wid >> 3;          // 0 or 1
    const int gwid  = wid & 7;           // 0..7 within group

    // Tables into registers (packed along feature axis).
    u64 R2[9][2], S2[6][2];
    #pragma unroll
    for (int k = 0; k < 9; k++) {
        float4 t = *(const float4*)&g_R[k][lane * 4];
        R2[k][0] = pk2(t.x, t.y); R2[k][1] = pk2(t.z, t.w);
    }
    #pragma unroll
    for (int k = 0; k < 6; k++) {
        float4 t = *(const float4*)&g_S[k][lane * 4];
        S2[k][0] = pk2(t.x, t.y); S2[k][1] = pk2(t.z, t.w);
    }

    const int T    = N / TILE_NODES;     // full tiles
    const int grid = gridDim.x;
    const int bid  = blockIdx.x;
    // Block-local tile count; group g handles local indices j with j%2==g.
    const int njt = (bid < T) ? (T - bid + grid - 1) / grid : 0;
    const int njg = (njt + 1 - grp) / 2;           // tiles for this group

    if (tid == 0) {
        #pragma unroll
        for (int s = 0; s < 2 * STAGES; s++) mbar_init(smem_base + 8 * s, 1);
    }
    __syncthreads();

    const bool producer = (tid == grp * 256);
    const uint32_t mb_base  = smem_base + 8 * (grp * STAGES);
    const uint32_t stg_base = smem_base + SMEM_STAGE0 + grp * STAGES * STAGE_BYTES;

    // Prime this group's pipeline.
    if (producer) {
        const int pre = njg < STAGES ? njg : STAGES;
        for (int k = 0; k < pre; k++) {
            const int t = bid + (2 * k + grp) * grid;
            const uint32_t stg = stg_base + k * STAGE_BYTES;
            const uint32_t mb  = mb_base + 8 * k;
            mbar_expect_tx(mb, STAGE_BYTES);
            bulk_g2s(stg, nf + (size_t)t * (TILE_NODES * 4 * NNF), NF_BYTES, mb);
            bulk_g2s(stg + NF_BYTES, c0 + (size_t)t * (TILE_NODES * 4), CH_BYTES, mb);
            bulk_g2s(stg + NF_BYTES + CH_BYTES,
                     ci + (size_t)t * (TILE_NODES * 4), CH_BYTES, mb);
        }
    }

    for (int k = 0; k < njg; k++) {
        const int rnd = k / STAGES;
        const int s   = k - rnd * STAGES;
        mbar_wait(mb_base + 8 * s, rnd & 1);

        const int t = bid + (2 * k + grp) * grid;
        const char* stg = smem + SMEM_STAGE0 + (grp * STAGES + s) * STAGE_BYTES;

        // Warp gwid computes nodes (2*gwid, 2*gwid+1) of this 16-node tile.
        const int ln0 = 2 * gwid;
        const char* rowA = stg + (size_t)ln0 * (4 * NNF * 4);
        const char* rowB = rowA + 4 * NNF * 4;

        float4 fsA  = *(const float4*)(rowA + lane * 16);
        float4 fvA0 = *(const float4*)(rowA + 512 + lane * 48);
        float4 fvA1 = *(const float4*)(rowA + 512 + lane * 48 + 16);
        float4 fvA2 = *(const float4*)(rowA + 512 + lane * 48 + 32);
        float4 q0A  = *(const float4*)(stg + NF_BYTES + ln0 * 16);
        float4 qiA  = *(const float4*)(stg + NF_BYTES + CH_BYTES + ln0 * 16);
        const float accA = node_partial(R2, S2, fsA, fvA0, fvA1, fvA2, q0A, qiA);

        float4 fsB  = *(const float4*)(rowB + lane * 16);
        float4 fvB0 = *(const float4*)(rowB + 512 + lane * 48);
        float4 fvB1 = *(const float4*)(rowB + 512 + lane * 48 + 16);
        float4 fvB2 = *(const float4*)(rowB + 512 + lane * 48 + 32);
        float4 q0B  = *(const float4*)(stg + NF_BYTES + ln0 * 16 + 16);
        float4 qiB  = *(const float4*)(stg + NF_BYTES + CH_BYTES + ln0 * 16 + 16);
        const float accB = node_partial(R2, S2, fsB, fvB0, fvB1, fvB2, q0B, qiB);

        u64 pr = pk2(accA, accB);
        #pragma unroll
        for (int off = 16; off; off >>= 1)
            pr = add2(pr, __shfl_down_sync(0xffffffffu, pr, off));
        if (lane == 0) {
            float2 o;
            upk2(pr, o.x, o.y);
            *(float2*)(out + (size_t)t * TILE_NODES + ln0) = o;
        }

        // Group-scoped barrier: all 256 threads of this group done reading s.
        asm volatile("bar.sync %0, 256;" :: "r"(grp + 1) : "memory");

        if (producer && k + STAGES < njg) {
            const int tn = bid + (2 * (k + STAGES) + grp) * grid;
            const uint32_t stgu = stg_base + s * STAGE_BYTES;
            const uint32_t mb   = mb_base + 8 * s;
            mbar_expect_tx(mb, STAGE_BYTES);
            bulk_g2s(stgu, nf + (size_t)tn * (TILE_NODES * 4 * NNF), NF_BYTES, mb);
            bulk_g2s(stgu + NF_BYTES, c0 + (size_t)tn * (TILE_NODES * 4), CH_BYTES, mb);
            bulk_g2s(stgu + NF_BYTES + CH_BYTES,
                     ci + (size_t)tn * (TILE_NODES * 4), CH_BYTES, mb);
        }
    }

    // Remainder nodes (N % 16) via direct global loads (not hit for 131072).
    const int rem_start = T * TILE_NODES;
    if (blockIdx.x == grid - 1 && rem_start < N) {
        for (int n = rem_start + wid; n < N; n += 16) {
            const float* row = nf + (size_t)n * (4 * NNF);
            float4 fs = *(const float4*)(row + lane * 4);
            const float* rv = row + NNF + 12 * lane;
            float4 f0 = *(const float4*)(rv);
            float4 f1 = *(const float4*)(rv + 4);
            float4 f2 = *(const float4*)(rv + 8);
            float4 q0 = *(const float4*)(c0 + 4 * (size_t)n);
            float4 qi = *(const float4*)(ci + 4 * (size_t)n);
            float acc = node_partial(R2, S2, fs, f0, f1, f2, q0, qi);
            #pragma unroll
            for (int off = 16; off; off >>= 1)
                acc += __shfl_down_sync(0xffffffffu, acc, off);
            if (lane == 0) out[n] = acc;
        }
    }
}

// ---------------------------------------------------------------------------
extern "C" void kernel_launch(void* const* d_in, const int* in_sizes, int n_in,
                              void* d_out, int out_size)
{
    const float* node_feats = (const float*)d_in[0];
    const float* charges_0  = (const float*)d_in[1];
    const float* charges_i  = (const float*)d_in[2];
    const float* Wa_s = (const float*)d_in[8];
    const float* Wa_v = (const float*)d_in[9];
    const float* b_a  = (const float*)d_in[10];
    const float* Wb_s = (const float*)d_in[11];
    const float* Wb_v = (const float*)d_in[12];
    const float* b_b  = (const float*)d_in[13];
    const float* W_ss = (const float*)d_in[14];
    const float* W_vv = (const float*)d_in[15];
    const float* W_sv = (const float*)d_in[16];
    const float* W_vs = (const float*)d_in[17];
    const float* Wd_s = (const float*)d_in[18];
    const float* Wd_v = (const float*)d_in[19];
    float* out = (float*)d_out;
    const int N = out_size;

    cudaFuncSetAttribute(energy_kernel,
                         cudaFuncAttributeMaxDynamicSharedMemorySize,
                         SMEM_TOTAL);

    precompute_kernel<<<96, 1024>>>(Wa_s, Wa_v, b_a, Wb_s, Wb_v, b_b,
                                    W_ss, W_vv, W_sv, W_vs, Wd_s, Wd_v);
    energy_kernel<<<148, 512, SMEM_TOTAL>>>(node_feats, charges_0, charges_i,
                                            out, N);
}